// round 4
// baseline (speedup 1.0000x reference)
#include <cuda_runtime.h>

// ---------------------------------------------------------------------------
// Binarized 5-layer MLP, B=32768:
//   L0: 784->256, L1-3: 256->256, L4: 256->10, each: binarize(a) @ binarize(W).T
//   then training-mode BatchNorm over batch; final softmax.
// Implementation: XNOR-popcount GEMM on ballot-packed bits, exact integer
// column stats (S1,S2) with int64 atomics, per-column affine (A,beta) from a
// finalize kernel, next layer binarizes previous H on the fly via ballot.
// ---------------------------------------------------------------------------

#define BATCH 32768
#define L0_IN 784
#define L0_WORDS 25   // ceil(784/32)
#define MID_WORDS 8   // 256/32
#define EPSV 1e-5

// Scratch (no allocations allowed -> __device__ globals)
__device__ unsigned int g_Xb[BATCH * L0_WORDS];      // packed input bits
__device__ unsigned int g_Wb0[256 * L0_WORDS];       // packed W0
__device__ unsigned int g_WbM[3][256 * MID_WORDS];   // packed W1..W3
__device__ unsigned int g_Wb4[10 * MID_WORDS];       // packed W4
__device__ short        g_H[2][BATCH * 256];         // ping-pong pre-BN activations
__device__ short        g_H4[BATCH * 10];            // last layer pre-BN
__device__ long long    g_S1[5][256];                // per-column sum(h)
__device__ long long    g_S2[5][256];                // per-column sum(h^2)
__device__ float2       g_norm[5][256];              // per-column (A, beta): y = A*h + beta

// ---------------------------------------------------------------------------
// zero the stat accumulators (graph replays must be deterministic)
__global__ void zero_stats_kernel() {
    int i = blockIdx.x * blockDim.x + threadIdx.x;
    if (i < 5 * 256) {
        g_S1[i >> 8][i & 255] = 0;
        g_S2[i >> 8][i & 255] = 0;
    }
}

// ---------------------------------------------------------------------------
// Binarize + pack a [rows, in_dim] float matrix into bits (bit = (v - sub) >= 0).
// One warp per row; bit j of word w corresponds to column 32*w + j.
// target selects the destination __device__ buffer (no host symbol lookups).
__global__ void pack_kernel(const float* __restrict__ src, int target,
                            int rows, int in_dim, int words, float sub) {
    unsigned int* dst;
    switch (target) {
        case 0: dst = g_Xb;     break;
        case 1: dst = g_Wb0;    break;
        case 2: dst = g_WbM[0]; break;
        case 3: dst = g_WbM[1]; break;
        case 4: dst = g_WbM[2]; break;
        default: dst = g_Wb4;   break;
    }
    int gw = (blockIdx.x * blockDim.x + threadIdx.x) >> 5;
    int lane = threadIdx.x & 31;
    if (gw >= rows) return;
    long base = (long)gw * in_dim;
    for (int w = 0; w < words; w++) {
        int c = (w << 5) + lane;
        bool p = (c < in_dim) && ((src[base + c] - sub) >= 0.0f);
        unsigned int word = __ballot_sync(0xffffffffu, p);
        if (lane == 0) dst[gw * words + w] = word;
    }
}

// ---------------------------------------------------------------------------
// Layer 0 GEMM: h = 784 - 2*popc(xor), 256 outputs, K=784 (25 words).
// Block: 256 threads = 8 warps. Each warp: 2 iters x 4 rows = 8 rows.
// Lane owns 8 columns (col = lane + 32*c8). Weights in smem, stride 25 (odd
// -> conflict-free). Per-lane register stat accumulation -> smem -> global i64.
__global__ __launch_bounds__(256) void gemm0_kernel() {
    __shared__ unsigned int sW[256 * L0_WORDS];   // 25.6 KB
    __shared__ int sS1[256], sS2[256];
    int tid = threadIdx.x;
    for (int i = tid; i < 256 * L0_WORDS; i += 256) sW[i] = g_Wb0[i];
    sS1[tid] = 0; sS2[tid] = 0;
    __syncthreads();

    int warp = tid >> 5, lane = tid & 31;
    int ls1[8], ls2[8];
#pragma unroll
    for (int c8 = 0; c8 < 8; c8++) { ls1[c8] = 0; ls2[c8] = 0; }

    for (int it = 0; it < 2; it++) {
        int row0 = blockIdx.x * 64 + warp * 8 + it * 4;
        unsigned int myw[4];
#pragma unroll
        for (int r = 0; r < 4; r++)
            myw[r] = (lane < L0_WORDS) ? g_Xb[(row0 + r) * L0_WORDS + lane] : 0u;

        int acc0[8], acc1[8], acc2[8], acc3[8];
#pragma unroll
        for (int c8 = 0; c8 < 8; c8++) { acc0[c8]=0; acc1[c8]=0; acc2[c8]=0; acc3[c8]=0; }

#pragma unroll 5
        for (int w = 0; w < L0_WORDS; w++) {
            unsigned aw0 = __shfl_sync(0xffffffffu, myw[0], w);
            unsigned aw1 = __shfl_sync(0xffffffffu, myw[1], w);
            unsigned aw2 = __shfl_sync(0xffffffffu, myw[2], w);
            unsigned aw3 = __shfl_sync(0xffffffffu, myw[3], w);
#pragma unroll
            for (int c8 = 0; c8 < 8; c8++) {
                unsigned wv = sW[(lane + (c8 << 5)) * L0_WORDS + w];
                acc0[c8] += __popc(aw0 ^ wv);
                acc1[c8] += __popc(aw1 ^ wv);
                acc2[c8] += __popc(aw2 ^ wv);
                acc3[c8] += __popc(aw3 ^ wv);
            }
        }
#pragma unroll
        for (int c8 = 0; c8 < 8; c8++) {
            int col = lane + (c8 << 5);
            int h0 = L0_IN - 2 * acc0[c8];
            int h1 = L0_IN - 2 * acc1[c8];
            int h2 = L0_IN - 2 * acc2[c8];
            int h3 = L0_IN - 2 * acc3[c8];
            g_H[0][(row0 + 0) * 256 + col] = (short)h0;
            g_H[0][(row0 + 1) * 256 + col] = (short)h1;
            g_H[0][(row0 + 2) * 256 + col] = (short)h2;
            g_H[0][(row0 + 3) * 256 + col] = (short)h3;
            ls1[c8] += h0 + h1 + h2 + h3;
            ls2[c8] += h0*h0 + h1*h1 + h2*h2 + h3*h3;
        }
    }
#pragma unroll
    for (int c8 = 0; c8 < 8; c8++) {
        int col = lane + (c8 << 5);
        atomicAdd(&sS1[col], ls1[c8]);
        atomicAdd(&sS2[col], ls2[c8]);
    }
    __syncthreads();
    atomicAdd((unsigned long long*)&g_S1[0][tid], (unsigned long long)(long long)sS1[tid]);
    atomicAdd((unsigned long long*)&g_S2[0][tid], (unsigned long long)(long long)sS2[tid]);
}

// ---------------------------------------------------------------------------
// Finalize BN affine for layer statIdx: y = A*h + beta, A = g*rsqrt(var+eps),
// beta = b - A*mean. Computed in double from exact integer sums.
__global__ void finalize_kernel(const float* __restrict__ g,
                                const float* __restrict__ b,
                                int statIdx, int ncols) {
    int c = threadIdx.x;
    if (c < ncols) {
        double m = (double)g_S1[statIdx][c] / (double)BATCH;
        double v = (double)g_S2[statIdx][c] / (double)BATCH - m * m;
        double r = 1.0 / sqrt(v + EPSV);
        double A = (double)g[c] * r;
        double beta = (double)b[c] - A * m;
        g_norm[statIdx][c] = make_float2((float)A, (float)beta);
    }
}

// ---------------------------------------------------------------------------
// Middle layers (1..3): binarize previous H on the fly (ballot), then
// 256x256 XNOR-popc GEMM with K=256 (8 words). 2 rows per iter, 4 iters,
// 8 warps -> 64 rows per block.
__global__ __launch_bounds__(256) void gemm_mid_kernel(int inBuf, int outBuf,
                                                       int wIdx, int statIdx) {
    __shared__ unsigned int sW[256 * 9];   // stride 9 (odd) -> conflict-free
    __shared__ float2 sN[256];
    __shared__ int sS1[256], sS2[256];
    const short* __restrict__ Hin = g_H[inBuf];
    short* __restrict__ Hout = g_H[outBuf];
    const unsigned int* __restrict__ Wb = g_WbM[wIdx];
    int tid = threadIdx.x;
    for (int i = tid; i < 256 * MID_WORDS; i += 256) {
        int col = i >> 3, w = i & 7;
        sW[col * 9 + w] = Wb[i];
    }
    sN[tid] = g_norm[statIdx - 1][tid];
    sS1[tid] = 0; sS2[tid] = 0;
    __syncthreads();

    int warp = tid >> 5, lane = tid & 31;
    int ls1[8], ls2[8];
#pragma unroll
    for (int c8 = 0; c8 < 8; c8++) { ls1[c8] = 0; ls2[c8] = 0; }

    for (int it = 0; it < 4; it++) {
        int row0 = blockIdx.x * 64 + warp * 8 + it * 2;
        unsigned aw0[8], aw1[8];
#pragma unroll
        for (int wi = 0; wi < 8; wi++) {
            int c = (wi << 5) + lane;
            float2 nb = sN[c];
            float h0 = (float)Hin[(row0 + 0) * 256 + c];
            float h1 = (float)Hin[(row0 + 1) * 256 + c];
            aw0[wi] = __ballot_sync(0xffffffffu, fmaf(nb.x, h0, nb.y) >= 0.0f);
            aw1[wi] = __ballot_sync(0xffffffffu, fmaf(nb.x, h1, nb.y) >= 0.0f);
        }
        int acc0[8], acc1[8];
#pragma unroll
        for (int c8 = 0; c8 < 8; c8++) { acc0[c8] = 0; acc1[c8] = 0; }
#pragma unroll
        for (int w = 0; w < 8; w++) {
#pragma unroll
            for (int c8 = 0; c8 < 8; c8++) {
                unsigned wv = sW[((c8 << 5) + lane) * 9 + w];
                acc0[c8] += __popc(aw0[w] ^ wv);
                acc1[c8] += __popc(aw1[w] ^ wv);
            }
        }
#pragma unroll
        for (int c8 = 0; c8 < 8; c8++) {
            int col = (c8 << 5) + lane;
            int h0 = 256 - 2 * acc0[c8];
            int h1 = 256 - 2 * acc1[c8];
            Hout[(row0 + 0) * 256 + col] = (short)h0;
            Hout[(row0 + 1) * 256 + col] = (short)h1;
            ls1[c8] += h0 + h1;
            ls2[c8] += h0 * h0 + h1 * h1;
        }
    }
#pragma unroll
    for (int c8 = 0; c8 < 8; c8++) {
        int col = (c8 << 5) + lane;
        atomicAdd(&sS1[col], ls1[c8]);
        atomicAdd(&sS2[col], ls2[c8]);
    }
    __syncthreads();
    atomicAdd((unsigned long long*)&g_S1[statIdx][tid], (unsigned long long)(long long)sS1[tid]);
    atomicAdd((unsigned long long*)&g_S2[statIdx][tid], (unsigned long long)(long long)sS2[tid]);
}

// ---------------------------------------------------------------------------
// Layer 4: 256 -> 10. Binarize H3 via ballot, then 10 columns by lanes 0..9.
__global__ __launch_bounds__(256) void gemm4_kernel() {
    __shared__ unsigned int sW[10 * MID_WORDS];
    __shared__ float2 sN[256];
    const short* __restrict__ Hin = g_H[1];
    int tid = threadIdx.x;
    if (tid < 10 * MID_WORDS) sW[tid] = g_Wb4[tid];
    sN[tid] = g_norm[3][tid];
    __syncthreads();

    int warp = tid >> 5, lane = tid & 31;
    const int ROWS = 16;
    int row0 = blockIdx.x * (8 * ROWS) + warp * ROWS;
    int ls1 = 0, ls2 = 0;
    for (int r = 0; r < ROWS; r++) {
        int row = row0 + r;
        unsigned aw[8];
#pragma unroll
        for (int wi = 0; wi < 8; wi++) {
            int c = (wi << 5) + lane;
            float2 nb = sN[c];
            float h = (float)Hin[row * 256 + c];
            aw[wi] = __ballot_sync(0xffffffffu, fmaf(nb.x, h, nb.y) >= 0.0f);
        }
        if (lane < 10) {
            int acc = 0;
#pragma unroll
            for (int w = 0; w < 8; w++)
                acc += __popc(aw[w] ^ sW[lane * MID_WORDS + w]);
            int h = 256 - 2 * acc;
            g_H4[row * 10 + lane] = (short)h;
            ls1 += h; ls2 += h * h;
        }
    }
    if (lane < 10) {
        atomicAdd((unsigned long long*)&g_S1[4][lane], (unsigned long long)(long long)ls1);
        atomicAdd((unsigned long long*)&g_S2[4][lane], (unsigned long long)(long long)ls2);
    }
}

// ---------------------------------------------------------------------------
// Final BN + softmax, thread per row.
__global__ void softmax_kernel(float* __restrict__ out) {
    __shared__ float2 sN[10];
    if (threadIdx.x < 10) sN[threadIdx.x] = g_norm[4][threadIdx.x];
    __syncthreads();
    int row = blockIdx.x * blockDim.x + threadIdx.x;
    if (row >= BATCH) return;
    float y[10];
    float mx = -1e30f;
#pragma unroll
    for (int i = 0; i < 10; i++) {
        y[i] = fmaf(sN[i].x, (float)g_H4[row * 10 + i], sN[i].y);
        mx = fmaxf(mx, y[i]);
    }
    float s = 0.0f;
#pragma unroll
    for (int i = 0; i < 10; i++) {
        y[i] = expf(y[i] - mx);
        s += y[i];
    }
    float inv = 1.0f / s;
#pragma unroll
    for (int i = 0; i < 10; i++)
        out[row * 10 + i] = y[i] * inv;
}

// ---------------------------------------------------------------------------
extern "C" void kernel_launch(void* const* d_in, const int* in_sizes, int n_in,
                              void* d_out, int out_size) {
    const float* x = (const float*)d_in[0];
    const float *W[5], *G[5], *Bv[5];
    // setup_inputs dict order interleaves (W,g,b); signature order groups them.
    // Discriminate via in_sizes[2]: 256 -> interleaved (g0), 65536 -> grouped (W1).
    bool interleaved = (n_in >= 16) && (in_sizes[2] == 256) && (in_sizes[3] == 256);
    if (interleaved) {
        int idx = 1;
        for (int k = 0; k < 5; k++) {
            W[k]  = (const float*)d_in[idx + 0];
            G[k]  = (const float*)d_in[idx + 1];
            Bv[k] = (const float*)d_in[idx + 2];
            idx += 3;
        }
    } else {
        for (int k = 0; k < 5; k++) {
            W[k]  = (const float*)d_in[1 + k];
            G[k]  = (const float*)d_in[6 + k];
            Bv[k] = (const float*)d_in[11 + k];
        }
    }

    // 1) reset stats (graph replay determinism)
    zero_stats_kernel<<<5, 256>>>();

    // 2) pack input + all weights
    pack_kernel<<<(BATCH * 32) / 256, 256>>>(x,    0, BATCH, L0_IN, L0_WORDS, 0.5f);
    pack_kernel<<<(256 * 32) / 256,   256>>>(W[0], 1, 256,   L0_IN, L0_WORDS, 0.0f);
    pack_kernel<<<(256 * 32) / 256,   256>>>(W[1], 2, 256,   256,   MID_WORDS, 0.0f);
    pack_kernel<<<(256 * 32) / 256,   256>>>(W[2], 3, 256,   256,   MID_WORDS, 0.0f);
    pack_kernel<<<(256 * 32) / 256,   256>>>(W[3], 4, 256,   256,   MID_WORDS, 0.0f);
    pack_kernel<<<2,                  256>>>(W[4], 5, 10,    256,   MID_WORDS, 0.0f);

    // 3) layer pipeline
    gemm0_kernel<<<BATCH / 64, 256>>>();
    finalize_kernel<<<1, 256>>>(G[0], Bv[0], 0, 256);

    gemm_mid_kernel<<<BATCH / 64, 256>>>(0, 1, 0, 1);
    finalize_kernel<<<1, 256>>>(G[1], Bv[1], 1, 256);

    gemm_mid_kernel<<<BATCH / 64, 256>>>(1, 0, 1, 2);
    finalize_kernel<<<1, 256>>>(G[2], Bv[2], 2, 256);

    gemm_mid_kernel<<<BATCH / 64, 256>>>(0, 1, 2, 3);
    finalize_kernel<<<1, 256>>>(G[3], Bv[3], 3, 256);

    gemm4_kernel<<<BATCH / 128, 256>>>();
    finalize_kernel<<<1, 256>>>(G[4], Bv[4], 4, 10);

    softmax_kernel<<<BATCH / 256, 256>>>((float*)d_out);
    (void)in_sizes; (void)out_size;
}

// round 5
// speedup vs baseline: 1.6010x; 1.6010x over previous
#include <cuda_runtime.h>

// ---------------------------------------------------------------------------
// Binarized 5-layer MLP, B=32768:
//   L0: 784->256, L1-3: 256->256, L4: 256->10, each: binarize(a) @ binarize(W).T
//   then training-mode BatchNorm over batch; final softmax.
// XNOR-popcount GEMM on ballot-packed bits; exact integer column stats with
// int64 atomics; per-column BN affine recomputed per consumer block (exact
// double math). Weight smem uses padded odd-ish strides so LDS.128 is
// bank-conflict-free. 8 launches total.
// ---------------------------------------------------------------------------

#define BATCH 32768
#define L0_IN 784
#define L0_WORDS 25    // ceil(784/32)
#define L0_WPAD 28     // padded stride (28*{0..7} mod 32 = distinct 4-groups -> LDS.128 ok)
#define MID_WORDS 8    // 256/32
#define MID_WPAD 12    // 12*{0..7} mod 32 = distinct 4-groups -> LDS.128 ok
#define EPSV 1e-5

// Scratch (no allocations allowed -> __device__ globals)
__device__ unsigned int g_Xb[BATCH * L0_WORDS];      // packed input bits
__device__ unsigned int g_Wb0[256 * L0_WORDS];       // packed W0
__device__ unsigned int g_WbM[3][256 * MID_WORDS];   // packed W1..W3
__device__ unsigned int g_Wb4[10 * MID_WORDS];       // packed W4
__device__ short        g_H[2][BATCH * 256];         // ping-pong pre-BN activations
__device__ short        g_H4[BATCH * 10];            // last layer pre-BN
__device__ long long    g_S1[5][256];                // per-column sum(h)
__device__ long long    g_S2[5][256];                // per-column sum(h^2)

// ---------------------------------------------------------------------------
__global__ void zero_stats_kernel() {
    int i = blockIdx.x * blockDim.x + threadIdx.x;
    if (i < 5 * 256) {
        g_S1[i >> 8][i & 255] = 0;
        g_S2[i >> 8][i & 255] = 0;
    }
}

// ---------------------------------------------------------------------------
// One warp packs one row: bit j of word w = ((src[row][32w+j] - sub) >= 0).
__device__ __forceinline__ void pack_rows(const float* __restrict__ src,
                                          unsigned int* __restrict__ dst,
                                          int row, int rows, int in_dim,
                                          int words, float sub) {
    if (row >= rows) return;
    int lane = threadIdx.x & 31;
    long base = (long)row * in_dim;
    for (int w = 0; w < words; w++) {
        int c = (w << 5) + lane;
        bool p = (c < in_dim) && ((src[base + c] - sub) >= 0.0f);
        unsigned int m = __ballot_sync(0xffffffffu, p);
        if (lane == 0) dst[row * words + w] = m;
    }
}

// Single prep kernel: packs x and all 5 weight matrices. Block ranges:
//   [0,4096)      : x     (8 rows/block, 32768 rows)
//   [4096,4128)   : W0    (256 rows)
//   [4128,4160)   : W1
//   [4160,4192)   : W2
//   [4192,4224)   : W3
//   [4224,4226)   : W4    (10 rows)
__global__ __launch_bounds__(256) void prep_kernel(
    const float* __restrict__ x,  const float* __restrict__ W0,
    const float* __restrict__ W1, const float* __restrict__ W2,
    const float* __restrict__ W3, const float* __restrict__ W4) {
    int b = blockIdx.x;
    int warp = threadIdx.x >> 5;
    if (b < 4096) {
        pack_rows(x, g_Xb, b * 8 + warp, BATCH, L0_IN, L0_WORDS, 0.5f);
    } else if (b < 4128) {
        pack_rows(W0, g_Wb0, (b - 4096) * 8 + warp, 256, L0_IN, L0_WORDS, 0.0f);
    } else if (b < 4160) {
        pack_rows(W1, g_WbM[0], (b - 4128) * 8 + warp, 256, 256, MID_WORDS, 0.0f);
    } else if (b < 4192) {
        pack_rows(W2, g_WbM[1], (b - 4160) * 8 + warp, 256, 256, MID_WORDS, 0.0f);
    } else if (b < 4224) {
        pack_rows(W3, g_WbM[2], (b - 4192) * 8 + warp, 256, 256, MID_WORDS, 0.0f);
    } else {
        pack_rows(W4, g_Wb4, (b - 4224) * 8 + warp, 10, 256, MID_WORDS, 0.0f);
    }
}

// ---------------------------------------------------------------------------
// Compute per-column BN affine y = A*h + beta for layer `layer` from exact
// integer stats (done redundantly per block; 256 threads, one col each).
__device__ __forceinline__ void compute_norm(float2* sN, int layer,
                                             const float* __restrict__ g,
                                             const float* __restrict__ b,
                                             int ncols) {
    int c = threadIdx.x;
    if (c < ncols) {
        double m = (double)g_S1[layer][c] / (double)BATCH;
        double v = (double)g_S2[layer][c] / (double)BATCH - m * m;
        double r = 1.0 / sqrt(v + EPSV);
        double A = (double)g[c] * r;
        double beta = (double)b[c] - A * m;
        sN[c] = make_float2((float)A, (float)beta);
    }
}

// ---------------------------------------------------------------------------
// Layer 0: h = 784 - 2*popc(xor), K=784 (25 words, padded to 28 with zeros;
// activation lanes >=25 also hold 0, so padding contributes 0).
// Block = 8 warps; warp does 2 iters x 4 rows = 8 rows; block = 64 rows.
// Lane owns 8 columns (col = lane + 32*c8); weights via conflict-free LDS.128.
__global__ __launch_bounds__(256) void gemm0_kernel() {
    __shared__ __align__(16) unsigned int sW[256 * L0_WPAD];  // 28.7 KB
    __shared__ int sS1[256], sS2[256];
    int tid = threadIdx.x;
    for (int idx = tid; idx < 256 * L0_WPAD; idx += 256) {
        int col = idx / L0_WPAD, w = idx - col * L0_WPAD;
        sW[idx] = (w < L0_WORDS) ? g_Wb0[col * L0_WORDS + w] : 0u;
    }
    sS1[tid] = 0; sS2[tid] = 0;
    __syncthreads();

    int warp = tid >> 5, lane = tid & 31;
    int ls1[8], ls2[8];
#pragma unroll
    for (int c8 = 0; c8 < 8; c8++) { ls1[c8] = 0; ls2[c8] = 0; }

    for (int it = 0; it < 2; it++) {
        int row0 = blockIdx.x * 64 + warp * 8 + it * 4;
        unsigned int myw[4];
#pragma unroll
        for (int r = 0; r < 4; r++)
            myw[r] = (lane < L0_WORDS) ? g_Xb[(row0 + r) * L0_WORDS + lane] : 0u;

        int acc[4][8];
#pragma unroll
        for (int r = 0; r < 4; r++)
#pragma unroll
            for (int c8 = 0; c8 < 8; c8++) acc[r][c8] = 0;

#pragma unroll 1
        for (int q = 0; q < 7; q++) {           // 7 quads cover words 0..27
            unsigned int aw[4][4];
#pragma unroll
            for (int r = 0; r < 4; r++)
#pragma unroll
                for (int k = 0; k < 4; k++)
                    aw[r][k] = __shfl_sync(0xffffffffu, myw[r], (q << 2) + k);
#pragma unroll
            for (int c8 = 0; c8 < 8; c8++) {
                uint4 wv = *(const uint4*)&sW[(lane + (c8 << 5)) * L0_WPAD + (q << 2)];
#pragma unroll
                for (int r = 0; r < 4; r++) {
                    acc[r][c8] += __popc(aw[r][0] ^ wv.x) + __popc(aw[r][1] ^ wv.y)
                                + __popc(aw[r][2] ^ wv.z) + __popc(aw[r][3] ^ wv.w);
                }
            }
        }
#pragma unroll
        for (int c8 = 0; c8 < 8; c8++) {
            int col = lane + (c8 << 5);
#pragma unroll
            for (int r = 0; r < 4; r++) {
                int h = L0_IN - 2 * acc[r][c8];
                g_H[0][(row0 + r) * 256 + col] = (short)h;
                ls1[c8] += h;
                ls2[c8] += h * h;
            }
        }
    }
#pragma unroll
    for (int c8 = 0; c8 < 8; c8++) {
        int col = lane + (c8 << 5);
        atomicAdd(&sS1[col], ls1[c8]);
        atomicAdd(&sS2[col], ls2[c8]);
    }
    __syncthreads();
    atomicAdd((unsigned long long*)&g_S1[0][tid], (unsigned long long)(long long)sS1[tid]);
    atomicAdd((unsigned long long*)&g_S2[0][tid], (unsigned long long)(long long)sS2[tid]);
}

// ---------------------------------------------------------------------------
// Middle layers (1..3): compute prev-layer BN affine in-block, binarize prev H
// on the fly (ballot), 256x256 XNOR-popc GEMM, K=256 (2 quads).
// Warp does 2 iters x 4 rows = 8 rows; block = 64 rows.
__global__ __launch_bounds__(256) void gemm_mid_kernel(
    int inBuf, int outBuf, int wIdx,
    const float* __restrict__ gPrev, const float* __restrict__ bPrev,
    int statIdx) {
    __shared__ __align__(16) unsigned int sW[256 * MID_WPAD];  // 12.3 KB
    __shared__ float2 sN[256];
    __shared__ int sS1[256], sS2[256];
    const short* __restrict__ Hin = g_H[inBuf];
    short* __restrict__ Hout = g_H[outBuf];
    const unsigned int* __restrict__ Wb = g_WbM[wIdx];
    int tid = threadIdx.x;
    for (int i = tid; i < 256 * MID_WORDS; i += 256) {
        int col = i >> 3, w = i & 7;
        sW[col * MID_WPAD + w] = Wb[i];
    }
    compute_norm(sN, statIdx - 1, gPrev, bPrev, 256);
    sS1[tid] = 0; sS2[tid] = 0;
    __syncthreads();

    int warp = tid >> 5, lane = tid & 31;
    int ls1[8], ls2[8];
#pragma unroll
    for (int c8 = 0; c8 < 8; c8++) { ls1[c8] = 0; ls2[c8] = 0; }

    for (int it = 0; it < 2; it++) {
        int row0 = blockIdx.x * 64 + warp * 8 + it * 4;
        unsigned int aw[4][8];
#pragma unroll
        for (int r = 0; r < 4; r++) {
            const short* hp = &Hin[(row0 + r) * 256];
#pragma unroll
            for (int wi = 0; wi < 8; wi++) {
                int c = (wi << 5) + lane;
                float2 nb = sN[c];
                float h = (float)hp[c];
                aw[r][wi] = __ballot_sync(0xffffffffu, fmaf(nb.x, h, nb.y) >= 0.0f);
            }
        }
        int acc[4][8];
#pragma unroll
        for (int r = 0; r < 4; r++)
#pragma unroll
            for (int c8 = 0; c8 < 8; c8++) acc[r][c8] = 0;

#pragma unroll
        for (int q = 0; q < 2; q++) {
#pragma unroll
            for (int c8 = 0; c8 < 8; c8++) {
                uint4 wv = *(const uint4*)&sW[((c8 << 5) + lane) * MID_WPAD + (q << 2)];
#pragma unroll
                for (int r = 0; r < 4; r++) {
                    acc[r][c8] += __popc(aw[r][(q << 2) + 0] ^ wv.x)
                                + __popc(aw[r][(q << 2) + 1] ^ wv.y)
                                + __popc(aw[r][(q << 2) + 2] ^ wv.z)
                                + __popc(aw[r][(q << 2) + 3] ^ wv.w);
                }
            }
        }
#pragma unroll
        for (int c8 = 0; c8 < 8; c8++) {
            int col = (c8 << 5) + lane;
#pragma unroll
            for (int r = 0; r < 4; r++) {
                int h = 256 - 2 * acc[r][c8];
                Hout[(row0 + r) * 256 + col] = (short)h;
                ls1[c8] += h;
                ls2[c8] += h * h;
            }
        }
    }
#pragma unroll
    for (int c8 = 0; c8 < 8; c8++) {
        int col = (c8 << 5) + lane;
        atomicAdd(&sS1[col], ls1[c8]);
        atomicAdd(&sS2[col], ls2[c8]);
    }
    __syncthreads();
    atomicAdd((unsigned long long*)&g_S1[statIdx][tid], (unsigned long long)(long long)sS1[tid]);
    atomicAdd((unsigned long long*)&g_S2[statIdx][tid], (unsigned long long)(long long)sS2[tid]);
}

// ---------------------------------------------------------------------------
// Layer 4: 256 -> 10. Computes layer-3 BN affine in-block, binarizes H3 via
// ballot, 10 output columns handled by lanes 0..9.
__global__ __launch_bounds__(256) void gemm4_kernel(
    const float* __restrict__ g3, const float* __restrict__ b3) {
    __shared__ unsigned int sW[10 * MID_WORDS];
    __shared__ float2 sN[256];
    const short* __restrict__ Hin = g_H[1];
    int tid = threadIdx.x;
    if (tid < 10 * MID_WORDS) sW[tid] = g_Wb4[tid];
    compute_norm(sN, 3, g3, b3, 256);
    __syncthreads();

    int warp = tid >> 5, lane = tid & 31;
    const int ROWS = 16;
    int row0 = blockIdx.x * (8 * ROWS) + warp * ROWS;
    int ls1 = 0, ls2 = 0;
    for (int r = 0; r < ROWS; r++) {
        int row = row0 + r;
        unsigned int aw[8];
#pragma unroll
        for (int wi = 0; wi < 8; wi++) {
            int c = (wi << 5) + lane;
            float2 nb = sN[c];
            float h = (float)Hin[row * 256 + c];
            aw[wi] = __ballot_sync(0xffffffffu, fmaf(nb.x, h, nb.y) >= 0.0f);
        }
        if (lane < 10) {
            int acc = 0;
#pragma unroll
            for (int w = 0; w < 8; w++)
                acc += __popc(aw[w] ^ sW[lane * MID_WORDS + w]);
            int h = 256 - 2 * acc;
            g_H4[row * 10 + lane] = (short)h;
            ls1 += h; ls2 += h * h;
        }
    }
    if (lane < 10) {
        atomicAdd((unsigned long long*)&g_S1[4][lane], (unsigned long long)(long long)ls1);
        atomicAdd((unsigned long long*)&g_S2[4][lane], (unsigned long long)(long long)ls2);
    }
}

// ---------------------------------------------------------------------------
// Final BN (computed in-block from stats) + softmax, thread per row.
__global__ __launch_bounds__(256) void softmax_kernel(
    const float* __restrict__ g4, const float* __restrict__ b4,
    float* __restrict__ out) {
    __shared__ float2 sN[10];
    if (threadIdx.x < 10) {
        int c = threadIdx.x;
        double m = (double)g_S1[4][c] / (double)BATCH;
        double v = (double)g_S2[4][c] / (double)BATCH - m * m;
        double r = 1.0 / sqrt(v + EPSV);
        double A = (double)g4[c] * r;
        sN[c] = make_float2((float)A, (float)((double)b4[c] - A * m));
    }
    __syncthreads();
    int row = blockIdx.x * blockDim.x + threadIdx.x;
    if (row >= BATCH) return;
    float y[10];
    float mx = -1e30f;
#pragma unroll
    for (int i = 0; i < 10; i++) {
        y[i] = fmaf(sN[i].x, (float)g_H4[row * 10 + i], sN[i].y);
        mx = fmaxf(mx, y[i]);
    }
    float s = 0.0f;
#pragma unroll
    for (int i = 0; i < 10; i++) {
        y[i] = expf(y[i] - mx);
        s += y[i];
    }
    float inv = 1.0f / s;
#pragma unroll
    for (int i = 0; i < 10; i++)
        out[row * 10 + i] = y[i] * inv;
}

// ---------------------------------------------------------------------------
extern "C" void kernel_launch(void* const* d_in, const int* in_sizes, int n_in,
                              void* d_out, int out_size) {
    const float* x = (const float*)d_in[0];
    const float *W[5], *G[5], *Bv[5];
    // setup_inputs dict order interleaves (W,g,b); signature order groups them.
    bool interleaved = (n_in >= 16) && (in_sizes[2] == 256) && (in_sizes[3] == 256);
    if (interleaved) {
        int idx = 1;
        for (int k = 0; k < 5; k++) {
            W[k]  = (const float*)d_in[idx + 0];
            G[k]  = (const float*)d_in[idx + 1];
            Bv[k] = (const float*)d_in[idx + 2];
            idx += 3;
        }
    } else {
        for (int k = 0; k < 5; k++) {
            W[k]  = (const float*)d_in[1 + k];
            G[k]  = (const float*)d_in[6 + k];
            Bv[k] = (const float*)d_in[11 + k];
        }
    }

    // Launch order chosen so ncu (-s 5 -c 1) profiles a gemm_mid next round.
    zero_stats_kernel<<<5, 256>>>();                                   // 1
    prep_kernel<<<4226, 256>>>(x, W[0], W[1], W[2], W[3], W[4]);       // 2
    gemm0_kernel<<<BATCH / 64, 256>>>();                               // 3
    gemm_mid_kernel<<<BATCH / 64, 256>>>(0, 1, 0, G[0], Bv[0], 1);     // 4
    gemm_mid_kernel<<<BATCH / 64, 256>>>(1, 0, 1, G[1], Bv[1], 2);     // 5
    gemm_mid_kernel<<<BATCH / 64, 256>>>(0, 1, 2, G[2], Bv[2], 3);     // 6 <- profiled
    gemm4_kernel<<<BATCH / 128, 256>>>(G[3], Bv[3]);                   // 7
    softmax_kernel<<<BATCH / 256, 256>>>(G[4], Bv[4], (float*)d_out);  // 8
    (void)out_size;
}